// round 8
// baseline (speedup 1.0000x reference)
#include <cuda_runtime.h>

#define NN 8192
typedef unsigned long long u64;

// ---------------- scratch (__device__ globals: allocation-free) ----------------
__device__ float g_AT[67108864];      // 8192*8192 transposed A (256 MB)
__device__ float g_Z[NN * 512];       // Z of current layer (max 8192x512)
__device__ float g_H[NN * 512];       // H output of current layer
__device__ float g_t[NN];
__device__ float g_r[NN];

// ---------------- packed f32x2 helpers ----------------
__device__ __forceinline__ u64 dup2(float x) {
    u64 d; unsigned xi = __float_as_uint(x);
    asm("mov.b64 %0, {%1, %2};" : "=l"(d) : "r"(xi), "r"(xi));
    return d;
}
__device__ __forceinline__ void fma2(u64& d, u64 a, u64 b) {
    asm("fma.rn.f32x2 %0, %1, %2, %0;" : "+l"(d) : "l"(a), "l"(b));
}

__device__ __forceinline__ float pexp_sig(float m) {
    // exp(sigmoid(m)); sigmoid in (0,1) so no overflow anywhere
    float e = __expf(-m);
    float s = __fdividef(1.0f, 1.0f + e);
    return __expf(s);
}

// ---------------- transpose A -> g_AT ----------------
__global__ void transpose_kernel(const float* __restrict__ A) {
    __shared__ float tile[32][33];
    int bx = blockIdx.x * 32, by = blockIdx.y * 32;
    int tx = threadIdx.x, ty = threadIdx.y;
#pragma unroll
    for (int j = 0; j < 32; j += 8)
        tile[ty + j][tx] = A[(size_t)(by + ty + j) * NN + bx + tx];
    __syncthreads();
#pragma unroll
    for (int j = 0; j < 32; j += 8)
        g_AT[(size_t)(bx + ty + j) * NN + by + tx] = tile[tx][ty + j];
}

// ---------------- Z = relu(Hin @ W^T + b)  -> g_Z ----------------
// BM=64, BN=128, BK=16, 256 threads, 4x8 per-thread tile
__global__ __launch_bounds__(256) void zgemm_relu_kernel(
    const float* __restrict__ Hin_ext,   // nullptr -> g_H
    const float* __restrict__ W,         // [F, K]
    const float* __restrict__ bias,      // [F]
    int K, int F)
{
    __shared__ __align__(16) float Hs[16][68];
    __shared__ __align__(16) float Ws[16][128];

    const float* Hin = Hin_ext ? Hin_ext : (const float*)g_H;

    int tid = threadIdx.x;
    int m0 = blockIdx.y * 64, n0 = blockIdx.x * 128;
    int fm = tid >> 2, fk = (tid & 3) << 2;      // H tile fill
    int wn = tid >> 1, wk = (tid & 1) << 3;      // W tile fill
    int ty = tid >> 4, tx = tid & 15;            // compute mapping

    float acc[4][8];
#pragma unroll
    for (int i = 0; i < 4; i++)
#pragma unroll
        for (int j = 0; j < 8; j++) acc[i][j] = 0.0f;

    const float* hrow = Hin + (size_t)(m0 + fm) * K + fk;
    bool wv = (n0 + wn) < F;
    const float* wrow = W + (size_t)(n0 + wn) * K + wk;

    for (int k0 = 0; k0 < K; k0 += 16) {
        __syncthreads();
        float4 hv = *(const float4*)(hrow + k0);
        Hs[fk + 0][fm] = hv.x; Hs[fk + 1][fm] = hv.y;
        Hs[fk + 2][fm] = hv.z; Hs[fk + 3][fm] = hv.w;
        float4 w0 = make_float4(0.f, 0.f, 0.f, 0.f), w1 = w0;
        if (wv) { w0 = *(const float4*)(wrow + k0); w1 = *(const float4*)(wrow + k0 + 4); }
        Ws[wk + 0][wn] = w0.x; Ws[wk + 1][wn] = w0.y; Ws[wk + 2][wn] = w0.z; Ws[wk + 3][wn] = w0.w;
        Ws[wk + 4][wn] = w1.x; Ws[wk + 5][wn] = w1.y; Ws[wk + 6][wn] = w1.z; Ws[wk + 7][wn] = w1.w;
        __syncthreads();
#pragma unroll
        for (int kk = 0; kk < 16; kk++) {
            float4 a4 = *(const float4*)&Hs[kk][ty << 2];
            float4 b0 = *(const float4*)&Ws[kk][tx << 3];
            float4 b1 = *(const float4*)&Ws[kk][(tx << 3) + 4];
            float av[4] = {a4.x, a4.y, a4.z, a4.w};
            float bv[8] = {b0.x, b0.y, b0.z, b0.w, b1.x, b1.y, b1.z, b1.w};
#pragma unroll
            for (int i = 0; i < 4; i++)
#pragma unroll
                for (int j = 0; j < 8; j++) acc[i][j] = fmaf(av[i], bv[j], acc[i][j]);
        }
    }
    float bb[8];
#pragma unroll
    for (int j = 0; j < 8; j++) {
        int n = n0 + (tx << 3) + j;
        bb[j] = (n < F) ? bias[n] : 0.0f;
    }
#pragma unroll
    for (int i = 0; i < 4; i++) {
        int m = m0 + (ty << 2) + i;
        float* zr = g_Z + (size_t)m * F + n0 + (tx << 3);
#pragma unroll
        for (int j = 0; j < 8; j++) {
            int n = n0 + (tx << 3) + j;
            if (n < F) {
                float v = acc[i][j] + bb[j];
                zr[j] = v > 0.0f ? v : 0.0f;
            }
        }
    }
}

// ---------------- t[i] = Z[i]·tw + tb ; r[i] = Z[i]·rw + rb ----------------
__global__ void tr_kernel(const float* __restrict__ tw, const float* __restrict__ tb,
                          const float* __restrict__ rw, const float* __restrict__ rb,
                          int F)
{
    int row = blockIdx.x * blockDim.y + threadIdx.y;
    int lane = threadIdx.x;
    const float* z = g_Z + (size_t)row * F;
    float st = 0.f, sr = 0.f;
    for (int k = lane; k < F; k += 32) {
        float zv = z[k];
        st = fmaf(zv, tw[k], st);
        sr = fmaf(zv, rw[k], sr);
    }
#pragma unroll
    for (int o = 16; o; o >>= 1) {
        st += __shfl_xor_sync(0xffffffffu, st, o);
        sr += __shfl_xor_sync(0xffffffffu, sr, o);
    }
    if (lane == 0) { g_t[row] = st + tb[0]; g_r[row] = sr + rb[0]; }
}

// ---------------- fused attention: out = softmax(sigmoid(M)) @ Z ----------------
// M[i,j] = A[i,j]*t[j] + AT[i,j]*r[i];  p = exp(sigmoid(M));  out[i] = (p·Z)/sum(p)
// BM=64 rows, BN=128 cols, BK=16, 256 threads, 4 rows x 8 cols per thread (f32x2)
__global__ __launch_bounds__(256) void attn_kernel(
    const float* __restrict__ A, float* __restrict__ out_ext, int F)
{
    __shared__ __align__(16) float pT[16][68];   // transposed p tile [kk][row]
    __shared__ __align__(16) float Zs[16][128];  // Z tile [kk][col]
    __shared__ float ssum[64];

    float* out = out_ext ? out_ext : (float*)g_H;
    const float* __restrict__ AT = g_AT;
    const float* __restrict__ Z  = g_Z;
    const float* __restrict__ tp = g_t;

    int tid = threadIdx.x;
    int m0  = blockIdx.y * 64;
    int cb0 = blockIdx.x * 128;

    int fi = tid >> 2;              // p-fill row 0..63
    int fk = (tid & 3) << 2;        // p-fill kk base {0,4,8,12}
    int zk = tid >> 4;              // Z-fill kk 0..15
    int zc = (tid & 15) << 3;       // Z-fill col base
    int ty = tid >> 4;              // compute: rows ty*4..+3
    int tx = tid & 15;              // compute: cols tx*8..+7

    const float rv = g_r[m0 + fi];
    const float* Arow = A  + (size_t)(m0 + fi) * NN + fk;
    const float* Brow = AT + (size_t)(m0 + fi) * NN + fk;
    const float* Zrow = Z + (size_t)zk * F + cb0 + zc;
    bool zvalid = (cb0 + zc) < F;

    u64 acc[4][4];
#pragma unroll
    for (int i = 0; i < 4; i++)
#pragma unroll
        for (int j = 0; j < 4; j++) acc[i][j] = 0ull;

    float psum = 0.0f;

    for (int k0 = 0; k0 < NN; k0 += 16) {
        __syncthreads();
        // ---- p tile ----
        {
            float4 av = *(const float4*)(Arow + k0);
            float4 bv = *(const float4*)(Brow + k0);
            float4 tv = *(const float4*)(tp + k0 + fk);
            float p0 = pexp_sig(fmaf(av.x, tv.x, bv.x * rv));
            float p1 = pexp_sig(fmaf(av.y, tv.y, bv.y * rv));
            float p2 = pexp_sig(fmaf(av.z, tv.z, bv.z * rv));
            float p3 = pexp_sig(fmaf(av.w, tv.w, bv.w * rv));
            pT[fk + 0][fi] = p0; pT[fk + 1][fi] = p1;
            pT[fk + 2][fi] = p2; pT[fk + 3][fi] = p3;
            psum += (p0 + p1) + (p2 + p3);
        }
        // ---- Z tile ----
        {
            float4 v0 = make_float4(0.f, 0.f, 0.f, 0.f), v1 = v0;
            if (zvalid) {
                const float* zr = Zrow + (size_t)k0 * F;
                v0 = *(const float4*)zr;
                v1 = *(const float4*)(zr + 4);
            }
            *(float4*)&Zs[zk][zc]     = v0;
            *(float4*)&Zs[zk][zc + 4] = v1;
        }
        __syncthreads();
        // ---- compute: 16 FFMA2 per kk ----
#pragma unroll
        for (int kk = 0; kk < 16; kk++) {
            float4 pv = *(const float4*)&pT[kk][ty << 2];
            ulonglong2 z0 = *(const ulonglong2*)&Zs[kk][tx << 3];
            ulonglong2 z1 = *(const ulonglong2*)&Zs[kk][(tx << 3) + 4];
            u64 pd0 = dup2(pv.x), pd1 = dup2(pv.y), pd2 = dup2(pv.z), pd3 = dup2(pv.w);
            fma2(acc[0][0], pd0, z0.x); fma2(acc[0][1], pd0, z0.y);
            fma2(acc[0][2], pd0, z1.x); fma2(acc[0][3], pd0, z1.y);
            fma2(acc[1][0], pd1, z0.x); fma2(acc[1][1], pd1, z0.y);
            fma2(acc[1][2], pd1, z1.x); fma2(acc[1][3], pd1, z1.y);
            fma2(acc[2][0], pd2, z0.x); fma2(acc[2][1], pd2, z0.y);
            fma2(acc[2][2], pd2, z1.x); fma2(acc[2][3], pd2, z1.y);
            fma2(acc[3][0], pd3, z0.x); fma2(acc[3][1], pd3, z0.y);
            fma2(acc[3][2], pd3, z1.x); fma2(acc[3][3], pd3, z1.y);
        }
    }

    // row sums: 4 threads per row (fk groups) -> reduce within lane quads
    psum += __shfl_xor_sync(0xffffffffu, psum, 1);
    psum += __shfl_xor_sync(0xffffffffu, psum, 2);
    if ((tid & 3) == 0) ssum[fi] = psum;
    __syncthreads();

#pragma unroll
    for (int i = 0; i < 4; i++) {
        int row = m0 + (ty << 2) + i;
        float inv = 1.0f / ssum[(ty << 2) + i];
        float* orow = out + (size_t)row * F + cb0 + (tx << 3);
#pragma unroll
        for (int j = 0; j < 4; j++) {
            int c = cb0 + (tx << 3) + 2 * j;
            if (c < F) {
                float2 v = *(float2*)&acc[i][j];
                orow[2 * j]     = v.x * inv;
                orow[2 * j + 1] = v.y * inv;
            }
        }
    }
}

// ---------------- launch ----------------
extern "C" void kernel_launch(void* const* d_in, const int* in_sizes, int n_in,
                              void* d_out, int out_size)
{
    const float* X   = (const float*)d_in[0];
    const float* A   = (const float*)d_in[1];
    const float* W1w = (const float*)d_in[2];
    const float* W1b = (const float*)d_in[3];
    const float* t1w = (const float*)d_in[4];
    const float* t1b = (const float*)d_in[5];
    const float* r1w = (const float*)d_in[6];
    const float* r1b = (const float*)d_in[7];
    const float* W2w = (const float*)d_in[8];
    const float* W2b = (const float*)d_in[9];
    const float* t2w = (const float*)d_in[10];
    const float* t2b = (const float*)d_in[11];
    const float* r2w = (const float*)d_in[12];
    const float* r2b = (const float*)d_in[13];
    const float* W3w = (const float*)d_in[14];
    const float* W3b = (const float*)d_in[15];
    const float* t3w = (const float*)d_in[16];
    const float* t3b = (const float*)d_in[17];
    const float* r3w = (const float*)d_in[18];
    const float* r3b = (const float*)d_in[19];
    float* out = (float*)d_out;

    dim3 tb(32, 8);

    transpose_kernel<<<dim3(NN / 32, NN / 32), tb>>>(A);

    // layer 1: K=1024, F=512
    zgemm_relu_kernel<<<dim3(4, NN / 64), 256>>>(X, W1w, W1b, 1024, 512);
    tr_kernel<<<NN / 8, tb>>>(t1w, t1b, r1w, r1b, 512);
    attn_kernel<<<dim3(4, NN / 64), 256>>>(A, nullptr, 512);

    // layer 2: K=512, F=256   (reads g_H written by layer-1 attn)
    zgemm_relu_kernel<<<dim3(2, NN / 64), 256>>>(nullptr, W2w, W2b, 512, 256);
    tr_kernel<<<NN / 8, tb>>>(t2w, t2b, r2w, r2b, 256);
    attn_kernel<<<dim3(2, NN / 64), 256>>>(A, nullptr, 256);

    // layer 3: K=256, F=64 -> d_out
    zgemm_relu_kernel<<<dim3(1, NN / 64), 256>>>(nullptr, W3w, W3b, 256, 64);
    tr_kernel<<<NN / 8, tb>>>(t3w, t3b, r3w, r3b, 64);
    attn_kernel<<<dim3(1, NN / 64), 256>>>(A, out, 64);
}